// round 3
// baseline (speedup 1.0000x reference)
#include <cuda_runtime.h>
#include <cuda_fp16.h>

#define NB    50
#define HID   32
#define HALFD 16
#define JJ    16         // HID/2 packed pairs
#define VSTH  17         // u32 stride per bucket row (odd -> <=2-way bank conflicts)
#define TPB   256
#define RPT   4          // rows per thread

__device__ __forceinline__ unsigned long long pack2(float lo, float hi) {
    unsigned long long r;
    asm("mov.b64 %0, {%1, %2};" : "=l"(r) : "f"(lo), "f"(hi));
    return r;
}
__device__ __forceinline__ unsigned long long fma2(unsigned long long a,
                                                   unsigned long long b,
                                                   unsigned long long c) {
    unsigned long long d;
    asm("fma.rn.f32x2 %0, %1, %2, %3;" : "=l"(d) : "l"(a), "l"(b), "l"(c));
    return d;
}
__device__ __forceinline__ void unpack2(unsigned long long v, float& lo, float& hi) {
    asm("mov.b64 {%0, %1}, %2;" : "=f"(lo), "=f"(hi) : "l"(v));
}

__global__ __launch_bounds__(TPB)
void lightwin_kernel(const float2* __restrict__ x, const int* __restrict__ buckets,
                     const float* __restrict__ W1, const float* __restrict__ b1,
                     const float* __restrict__ W2, const float* __restrict__ b2v,
                     const float* __restrict__ Wh, const float* __restrict__ bh,
                     float* __restrict__ out, int B) {
    __shared__ __align__(16) float sAB[HID * 2];   // W1 row0 | W1 row1
    __shared__ __align__(16) float sC[HID];        // b1
    __shared__ unsigned sVh[NB * VSTH];            // V = Wh @ W2^T, half2 pairs, stride 17
    __shared__ float sc[NB];                       // c[b] = bh[b] + b2 . Wh[b]

    int tid = threadIdx.x;
    if (tid < HID * 2) sAB[tid] = W1[tid];
    if (tid < HID)     sC[tid]  = b1[tid];

    // Fused per-block precompute of combined head weights (25.6K FMA/block,
    // ~12.5 FMA/row amortized; Wh/W2 hot in L2 after first wave)
    for (int e = tid; e < NB * JJ; e += TPB) {
        int b = e >> 4, jj = e & 15;
        float s0 = 0.f, s1 = 0.f;
        const float* whp = Wh + b * HALFD;
        const float* w2a = W2 + (2 * jj)     * HALFD;
        const float* w2b = W2 + (2 * jj + 1) * HALFD;
        #pragma unroll
        for (int k = 0; k < HALFD; k++) {
            float wh = __ldg(&whp[k]);
            s0 = fmaf(__ldg(&w2a[k]), wh, s0);
            s1 = fmaf(__ldg(&w2b[k]), wh, s1);
        }
        __half2 h = __floats2half2_rn(s0, s1);
        sVh[b * VSTH + jj] = *reinterpret_cast<unsigned*>(&h);
    }
    for (int b = tid; b < NB; b += TPB) {
        float s = __ldg(&bh[b]);
        #pragma unroll
        for (int k = 0; k < HALFD; k++)
            s = fmaf(__ldg(&b2v[k]), __ldg(&Wh[b * HALFD + k]), s);
        sc[b] = s;
    }
    __syncthreads();

    int base = blockIdx.x * (TPB * RPT) + tid;

    unsigned long long x0d[RPT], x1d[RPT];
    float acc0[RPT], acc1[RPT];
    int   va[RPT];

    #pragma unroll
    for (int r = 0; r < RPT; r++) {
        int idx = base + r * TPB;
        bool p = idx < B;
        float2 xv = p ? __ldg(&x[idx]) : make_float2(0.f, 0.f);
        int b = p ? buckets[idx] : 0;
        b = ((unsigned)b < NB) ? b : (NB - 1);
        va[r]   = b * VSTH;
        x0d[r]  = pack2(xv.x, xv.x);
        x1d[r]  = pack2(xv.y, xv.y);
        acc0[r] = sc[b];            // head bias folded into accumulator
        acc1[r] = 0.f;
    }

    #pragma unroll
    for (int jj = 0; jj < JJ; jj++) {
        // warp-uniform weight pairs: broadcast LDS.64
        unsigned long long a2  = *(const unsigned long long*)&sAB[2 * jj];
        unsigned long long b2w = *(const unsigned long long*)&sAB[HID + 2 * jj];
        unsigned long long c2  = *(const unsigned long long*)&sC[2 * jj];
        #pragma unroll
        for (int r = 0; r < RPT; r++) {
            unsigned long long z = fma2(x1d[r], b2w, c2);
            z = fma2(x0d[r], a2, z);
            float z0, z1;
            unpack2(z, z0, z1);
            float h0 = fmaxf(z0, 0.f);
            float h1 = fmaxf(z1, 0.f);
            unsigned vh = sVh[va[r] + jj];          // one LDS.32 = both fp16 weights
            float2 vf = __half22float2(*reinterpret_cast<__half2*>(&vh));
            acc0[r] = fmaf(h0, vf.x, acc0[r]);
            acc1[r] = fmaf(h1, vf.y, acc1[r]);
        }
    }

    #pragma unroll
    for (int r = 0; r < RPT; r++) {
        int idx = base + r * TPB;
        if (idx < B) out[idx] = acc0[r] + acc1[r];
    }
}

extern "C" void kernel_launch(void* const* d_in, const int* in_sizes, int n_in,
                              void* d_out, int out_size) {
    const float2* x     = (const float2*)d_in[0];
    const int* buckets  = (const int*)d_in[1];
    const float* W1     = (const float*)d_in[2];
    const float* b1     = (const float*)d_in[3];
    const float* W2     = (const float*)d_in[4];
    const float* b2v    = (const float*)d_in[5];
    const float* Wh     = (const float*)d_in[6];
    const float* bh     = (const float*)d_in[7];
    float* out          = (float*)d_out;

    int B = in_sizes[1];  // buckets element count = row count

    int rows_per_block = TPB * RPT;
    int grid = (B + rows_per_block - 1) / rows_per_block;
    lightwin_kernel<<<grid, TPB>>>(x, buckets, W1, b1, W2, b2v, Wh, bh, out, B);
}

// round 4
// speedup vs baseline: 1.9961x; 1.9961x over previous
#include <cuda_runtime.h>
#include <cuda_fp16.h>

#define NB    50
#define HID   32
#define HALFD 16
#define JP    8          // jj-pairs: each handles 4 hidden units
#define VSTH  18         // u32 stride per bucket row (even -> 8B aligned LDS.64)
#define TPB   256
#define RPT   8          // rows per thread

// Precomputed combined head weights (scratch: __device__ globals, no alloc)
__device__ unsigned g_Vh[NB * VSTH];   // V = Wh @ W2^T, half2 pairs
__device__ float    g_c[NB];           // c[b] = bh[b] + b2 . Wh[b]

__global__ void precompute_kernel(const float* __restrict__ W2, const float* __restrict__ b2,
                                  const float* __restrict__ Wh, const float* __restrict__ bh) {
    int t  = blockIdx.x * blockDim.x + threadIdx.x;
    int nt = gridDim.x * blockDim.x;
    // V[b][j] = sum_k W2[j][k] * Wh[b][k]; pairs (2jj,2jj+1) packed as half2
    for (int e = t; e < NB * 16; e += nt) {
        int b = e / 16, jj = e % 16;
        float s0 = 0.f, s1 = 0.f;
        #pragma unroll
        for (int k = 0; k < HALFD; k++) {
            float wh = Wh[b * HALFD + k];
            s0 = fmaf(W2[(2 * jj)     * HALFD + k], wh, s0);
            s1 = fmaf(W2[(2 * jj + 1) * HALFD + k], wh, s1);
        }
        __half2 h = __floats2half2_rn(s0, s1);
        g_Vh[b * VSTH + jj] = *reinterpret_cast<unsigned*>(&h);
    }
    for (int b = t; b < NB; b += nt) {
        float s = bh[b];
        #pragma unroll
        for (int k = 0; k < HALFD; k++)
            s = fmaf(b2[k], Wh[b * HALFD + k], s);
        g_c[b] = s;
    }
}

__device__ __forceinline__ unsigned long long pack2(float lo, float hi) {
    unsigned long long r;
    asm("mov.b64 %0, {%1, %2};" : "=l"(r) : "f"(lo), "f"(hi));
    return r;
}
__device__ __forceinline__ unsigned long long fma2(unsigned long long a,
                                                   unsigned long long b,
                                                   unsigned long long c) {
    unsigned long long d;
    asm("fma.rn.f32x2 %0, %1, %2, %3;" : "=l"(d) : "l"(a), "l"(b), "l"(c));
    return d;
}
__device__ __forceinline__ void unpack2(unsigned long long v, float& lo, float& hi) {
    asm("mov.b64 {%0, %1}, %2;" : "=f"(lo), "=f"(hi) : "l"(v));
}

__global__ __launch_bounds__(TPB, 4)
void lightwin_kernel(const float2* __restrict__ x, const int* __restrict__ buckets,
                     const float* __restrict__ W1, const float* __restrict__ b1,
                     float* __restrict__ out, int B) {
    __shared__ __align__(16) float sAB[HID * 2];   // W1 row0 | W1 row1 (4-float groups 16B aligned)
    __shared__ __align__(16) float sC[HID];        // b1
    __shared__ __align__(8)  unsigned sVh[NB * VSTH];
    __shared__ float sc[NB];

    int tid = threadIdx.x;
    for (int i = tid; i < NB * VSTH; i += TPB) sVh[i] = g_Vh[i];
    if (tid < NB)      sc[tid]  = g_c[tid];
    if (tid < HID * 2) sAB[tid] = W1[tid];
    if (tid < HID)     sC[tid]  = b1[tid];
    __syncthreads();

    int base = blockIdx.x * (TPB * RPT) + tid;

    unsigned long long x0d[RPT], x1d[RPT], accp[RPT];
    int va[RPT];

    #pragma unroll
    for (int r = 0; r < RPT; r++) {
        int idx = base + r * TPB;
        bool p = idx < B;
        float2 xv = p ? __ldg(&x[idx]) : make_float2(0.f, 0.f);
        int b = p ? buckets[idx] : 0;
        b = ((unsigned)b < NB) ? b : (NB - 1);
        va[r]   = b * VSTH;
        x0d[r]  = pack2(xv.x, xv.x);
        x1d[r]  = pack2(xv.y, xv.y);
        accp[r] = pack2(sc[b], 0.f);   // head bias folded into packed accumulator
    }

    #pragma unroll
    for (int jp = 0; jp < JP; jp++) {
        // uniform weights: 4 hidden units per jp, LDS.128 broadcast each
        float4 a4 = *(const float4*)&sAB[4 * jp];
        float4 b4 = *(const float4*)&sAB[HID + 4 * jp];
        float4 c4 = *(const float4*)&sC[4 * jp];
        unsigned long long a2_0 = pack2(a4.x, a4.y), a2_1 = pack2(a4.z, a4.w);
        unsigned long long w2_0 = pack2(b4.x, b4.y), w2_1 = pack2(b4.z, b4.w);
        unsigned long long c2_0 = pack2(c4.x, c4.y), c2_1 = pack2(c4.z, c4.w);
        #pragma unroll
        for (int r = 0; r < RPT; r++) {
            // z for 4 hidden units (two packed pairs)
            unsigned long long z0 = fma2(x0d[r], a2_0, fma2(x1d[r], w2_0, c2_0));
            unsigned long long z1 = fma2(x0d[r], a2_1, fma2(x1d[r], w2_1, c2_1));
            float za, zb, zc, zd;
            unpack2(z0, za, zb);
            unpack2(z1, zc, zd);
            float h0 = fmaxf(za, 0.f), h1 = fmaxf(zb, 0.f);
            float h2 = fmaxf(zc, 0.f), h3 = fmaxf(zd, 0.f);
            // one LDS.64 fetches 4 fp16 gathered weights
            unsigned long long vv = *(const unsigned long long*)&sVh[va[r] + 2 * jp];
            unsigned vlo = (unsigned)vv, vhi = (unsigned)(vv >> 32);
            float2 vf0 = __half22float2(*reinterpret_cast<__half2*>(&vlo));
            float2 vf1 = __half22float2(*reinterpret_cast<__half2*>(&vhi));
            // packed dot-accumulate
            accp[r] = fma2(pack2(h0, h1), pack2(vf0.x, vf0.y), accp[r]);
            accp[r] = fma2(pack2(h2, h3), pack2(vf1.x, vf1.y), accp[r]);
        }
    }

    #pragma unroll
    for (int r = 0; r < RPT; r++) {
        int idx = base + r * TPB;
        float alo, ahi;
        unpack2(accp[r], alo, ahi);
        if (idx < B) out[idx] = alo + ahi;
    }
}

extern "C" void kernel_launch(void* const* d_in, const int* in_sizes, int n_in,
                              void* d_out, int out_size) {
    const float2* x     = (const float2*)d_in[0];
    const int* buckets  = (const int*)d_in[1];
    const float* W1     = (const float*)d_in[2];
    const float* b1     = (const float*)d_in[3];
    const float* W2     = (const float*)d_in[4];
    const float* b2v    = (const float*)d_in[5];
    const float* Wh     = (const float*)d_in[6];
    const float* bh     = (const float*)d_in[7];
    float* out          = (float*)d_out;

    int B = in_sizes[1];  // buckets element count = row count

    precompute_kernel<<<8, 256>>>(W2, b2v, Wh, bh);

    int rows_per_block = TPB * RPT;
    int grid = (B + rows_per_block - 1) / rows_per_block;
    lightwin_kernel<<<grid, TPB>>>(x, buckets, W1, b1, out, B);
}

// round 5
// speedup vs baseline: 2.3364x; 1.1704x over previous
#include <cuda_runtime.h>
#include <cuda_fp16.h>

#define NB    50
#define HID   32
#define HALFD 16
#define JJ    16         // HID/2 packed pairs
#define VSTH  17         // u32 stride per bucket row (odd -> <=2-way conflicts)
#define W2ST  17         // padded W2 row stride in smem (bank-spread for V compute)
#define TPB   256
#define RPT   8          // rows per thread

__device__ __forceinline__ unsigned long long pack2(float lo, float hi) {
    unsigned long long r;
    asm("mov.b64 %0, {%1, %2};" : "=l"(r) : "f"(lo), "f"(hi));
    return r;
}
__device__ __forceinline__ unsigned long long fma2(unsigned long long a,
                                                   unsigned long long b,
                                                   unsigned long long c) {
    unsigned long long d;
    asm("fma.rn.f32x2 %0, %1, %2, %3;" : "=l"(d) : "l"(a), "l"(b), "l"(c));
    return d;
}
__device__ __forceinline__ void unpack2(unsigned long long v, float& lo, float& hi) {
    asm("mov.b64 {%0, %1}, %2;" : "=f"(lo), "=f"(hi) : "l"(v));
}

__global__ __launch_bounds__(TPB, 4)
void lightwin_kernel(const float2* __restrict__ x, const int* __restrict__ buckets,
                     const float* __restrict__ W1, const float* __restrict__ b1,
                     const float* __restrict__ W2, const float* __restrict__ b2v,
                     const float* __restrict__ Wh, const float* __restrict__ bh,
                     float* __restrict__ out, int B) {
    __shared__ __align__(16) float sAB[HID * 2];     // W1 row0 | W1 row1
    __shared__ __align__(16) float sC[HID];          // b1
    __shared__ unsigned sVh[NB * VSTH];              // V = Wh @ W2^T, half2 pairs
    __shared__ float sc[NB];                         // c[b] = bh[b] + b2 . Wh[b]
    // staging for fused precompute (coalesced loads; bank-aware strides)
    __shared__ float sW2[HID * W2ST];                // W2[j][k] at j*17+k
    __shared__ float sWh[NB * HALFD];                // Wh[b][k] at b*16+k
    __shared__ float sB2[HALFD];
    __shared__ float sBh[NB];

    int tid = threadIdx.x;

    // ---- stage 1: coalesced global -> smem (~6 loads/thread, all unit-stride)
    if (tid < HID * 2)     sAB[tid] = W1[tid];
    if (tid < HID)         sC[tid]  = b1[tid];
    for (int i = tid; i < HID * HALFD; i += TPB)     // 512 floats
        sW2[(i >> 4) * W2ST + (i & 15)] = W2[i];
    for (int i = tid; i < NB * HALFD; i += TPB)      // 800 floats
        sWh[i] = Wh[i];
    if (tid < HALFD)       sB2[tid] = b2v[tid];
    if (tid < NB)          sBh[tid] = bh[tid];
    __syncthreads();

    // ---- stage 2: compute V (half2 pairs) and c from smem
    for (int e = tid; e < NB * JJ; e += TPB) {
        int b = e >> 4, jj = e & 15;
        const float* whp = &sWh[b * HALFD];
        const float* wa  = &sW2[(2 * jj)     * W2ST];
        const float* wb  = &sW2[(2 * jj + 1) * W2ST];
        float s0 = 0.f, s1 = 0.f;
        #pragma unroll
        for (int k = 0; k < HALFD; k++) {
            float wh = whp[k];
            s0 = fmaf(wa[k], wh, s0);
            s1 = fmaf(wb[k], wh, s1);
        }
        __half2 h = __floats2half2_rn(s0, s1);
        sVh[b * VSTH + jj] = *reinterpret_cast<unsigned*>(&h);
    }
    for (int b = tid; b < NB; b += TPB) {
        float s = sBh[b];
        #pragma unroll
        for (int k = 0; k < HALFD; k++)
            s = fmaf(sB2[k], sWh[b * HALFD + k], s);
        sc[b] = s;
    }
    __syncthreads();

    // ---- stage 3: main per-row loop (R2 structure: stride-17 LDS.32 gather)
    int base = blockIdx.x * (TPB * RPT) + tid;

    unsigned long long x0d[RPT], x1d[RPT];
    float acc0[RPT], acc1[RPT];
    int   va[RPT];

    #pragma unroll
    for (int r = 0; r < RPT; r++) {
        int idx = base + r * TPB;
        bool p = idx < B;
        float2 xv = p ? __ldg(&x[idx]) : make_float2(0.f, 0.f);
        int b = p ? buckets[idx] : 0;
        b = ((unsigned)b < NB) ? b : (NB - 1);
        va[r]   = b * VSTH;
        x0d[r]  = pack2(xv.x, xv.x);
        x1d[r]  = pack2(xv.y, xv.y);
        acc0[r] = sc[b];            // head bias folded into accumulator
        acc1[r] = 0.f;
    }

    #pragma unroll
    for (int jj = 0; jj < JJ; jj++) {
        // warp-uniform weight pairs: broadcast LDS.64
        unsigned long long a2  = *(const unsigned long long*)&sAB[2 * jj];
        unsigned long long b2w = *(const unsigned long long*)&sAB[HID + 2 * jj];
        unsigned long long c2  = *(const unsigned long long*)&sC[2 * jj];
        #pragma unroll
        for (int r = 0; r < RPT; r++) {
            unsigned long long z = fma2(x1d[r], b2w, c2);
            z = fma2(x0d[r], a2, z);
            float z0, z1;
            unpack2(z, z0, z1);
            float h0 = fmaxf(z0, 0.f);
            float h1 = fmaxf(z1, 0.f);
            unsigned vh = sVh[va[r] + jj];          // one LDS.32 = both fp16 weights
            float2 vf = __half22float2(*reinterpret_cast<__half2*>(&vh));
            acc0[r] = fmaf(h0, vf.x, acc0[r]);
            acc1[r] = fmaf(h1, vf.y, acc1[r]);
        }
    }

    #pragma unroll
    for (int r = 0; r < RPT; r++) {
        int idx = base + r * TPB;
        if (idx < B) out[idx] = acc0[r] + acc1[r];
    }
}

extern "C" void kernel_launch(void* const* d_in, const int* in_sizes, int n_in,
                              void* d_out, int out_size) {
    const float2* x     = (const float2*)d_in[0];
    const int* buckets  = (const int*)d_in[1];
    const float* W1     = (const float*)d_in[2];
    const float* b1     = (const float*)d_in[3];
    const float* W2     = (const float*)d_in[4];
    const float* b2v    = (const float*)d_in[5];
    const float* Wh     = (const float*)d_in[6];
    const float* bh     = (const float*)d_in[7];
    float* out          = (float*)d_out;

    int B = in_sizes[1];  // buckets element count = row count

    int rows_per_block = TPB * RPT;
    int grid = (B + rows_per_block - 1) / rows_per_block;
    lightwin_kernel<<<grid, TPB>>>(x, buckets, W1, b1, W2, b2v, Wh, bh, out, B);
}